// round 2
// baseline (speedup 1.0000x reference)
#include <cuda_runtime.h>

#define A_NUM 5
#define EPSV 1e-10f

// ---------------- batch-independent precomputed parameters ----------------
__device__ float g_Qt[64];
__device__ float g_G[64];   // Qt @ Qr
__device__ float g_Qy[64];
__device__ float g_wr[A_NUM];
__device__ float g_ws[A_NUM];
__device__ float g_t;

// 8x8 Cayley transform: Q = inv(I - Bm) @ (I + Bm), Bm = L - L^T,
// L[i+1][c] = b[i+c] for c in [0, i]  (exactly the reference's quirky mapping).
// Gauss-Jordan with partial pivoting (matches LAPACK-style solve numerics well
// within the 1e-3 tolerance).
__device__ void cayley8(const float* __restrict__ b, float* __restrict__ Q) {
    float Bm[8][8];
    for (int i = 0; i < 8; i++)
        for (int j = 0; j < 8; j++) Bm[i][j] = 0.0f;
    for (int i = 0; i < 7; i++)
        for (int c = 0; c <= i; c++) Bm[i + 1][c] = b[i + c];

    float A[8][16];
    for (int i = 0; i < 8; i++) {
        for (int j = 0; j < 8; j++) {
            float v = Bm[i][j] - Bm[j][i];
            float d = (i == j) ? 1.0f : 0.0f;
            A[i][j]     = d - v;   // I - Bm
            A[i][j + 8] = d + v;   // I + Bm
        }
    }
    // Gauss-Jordan with partial pivoting
    for (int k = 0; k < 8; k++) {
        int p = k;
        float best = fabsf(A[k][k]);
        for (int r = k + 1; r < 8; r++) {
            float v = fabsf(A[r][k]);
            if (v > best) { best = v; p = r; }
        }
        if (p != k) {
            for (int j = 0; j < 16; j++) {
                float tmp = A[k][j]; A[k][j] = A[p][j]; A[p][j] = tmp;
            }
        }
        float inv = 1.0f / A[k][k];
        for (int j = 0; j < 16; j++) A[k][j] *= inv;
        for (int r = 0; r < 8; r++) {
            if (r == k) continue;
            float f = A[r][k];
            for (int j = 0; j < 16; j++) A[r][j] -= f * A[k][j];
        }
    }
    for (int i = 0; i < 8; i++)
        for (int j = 0; j < 8; j++) Q[i * 8 + j] = A[i][j + 8];
}

__global__ void spdsru_prologue(const float* __restrict__ kr,
                                const float* __restrict__ kt,
                                const float* __restrict__ kphi,
                                const float* __restrict__ ks,
                                const float* __restrict__ br,
                                const float* __restrict__ bt,
                                const float* __restrict__ by) {
    __shared__ float sQr[64];
    __shared__ float sQt[64];
    int tid = threadIdx.x;
    if (tid < 3) {
        const float* bias = (tid == 0) ? br : ((tid == 1) ? bt : by);
        float Q[64];
        cayley8(bias, Q);
        if (tid == 0) {
            for (int i = 0; i < 64; i++) sQr[i] = Q[i];
        } else if (tid == 1) {
            for (int i = 0; i < 64; i++) { sQt[i] = Q[i]; g_Qt[i] = Q[i]; }
        } else {
            for (int i = 0; i < 64; i++) g_Qy[i] = Q[i];
        }
    }
    __syncthreads();
    if (tid == 0) {
        // G = Qt @ Qr
        for (int i = 0; i < 8; i++) {
            for (int j = 0; j < 8; j++) {
                float s = 0.0f;
                for (int k = 0; k < 8; k++) s += sQt[i * 8 + k] * sQr[k * 8 + j];
                g_G[i * 8 + j] = s;
            }
        }
        // normalized squared weights
        float r2[A_NUM], s2[A_NUM], sr = 0.0f, ss = 0.0f;
        for (int a = 0; a < A_NUM; a++) {
            r2[a] = kr[a] * kr[a]; sr += r2[a];
            s2[a] = ks[a] * ks[a]; ss += s2[a];
        }
        float ir = 1.0f / (sr + EPSV);
        float is = 1.0f / (ss + EPSV);
        for (int a = 0; a < A_NUM; a++) {
            g_wr[a] = r2[a] * ir;
            g_ws[a] = s2[a] * is;
        }
        float t2 = kt[0] * kt[0];
        g_t = t2 / (t2 + kphi[0] * kphi[0] + EPSV);
    }
}

// ---------------- main streaming kernel ----------------
// 8 threads per batch element; thread j owns row j of every 8x8 matrix.
// Congruence transform C = Q * A * Q^T:
//   step 1: Brow_j = Arow_j * Q^T         (thread-local, Q broadcast from smem)
//   step 2: Crow_j = sum_i Q[j][i]*Brow_i (rows gathered via width-8 shuffles)
__device__ __forceinline__ void congruence8(const float* __restrict__ a,
                                            const float* __restrict__ Qs,  // smem, stride 9
                                            int j,
                                            float* __restrict__ c) {
    float bb[8];
#pragma unroll
    for (int k = 0; k < 8; k++) {
        float s = 0.0f;
#pragma unroll
        for (int l = 0; l < 8; l++) s = fmaf(a[l], Qs[k * 9 + l], s);
        bb[k] = s;
    }
#pragma unroll
    for (int k = 0; k < 8; k++) c[k] = 0.0f;
#pragma unroll
    for (int i = 0; i < 8; i++) {
        float qji = Qs[j * 9 + i];
#pragma unroll
        for (int k = 0; k < 8; k++) {
            float bik = __shfl_sync(0xffffffffu, bb[k], i, 8);
            c[k] = fmaf(qji, bik, c[k]);
        }
    }
}

__global__ void __launch_bounds__(256)
spdsru_main(const float* __restrict__ x,
            const float* __restrict__ states,
            float* __restrict__ out,
            float* __restrict__ outst) {
    __shared__ float sQt[72], sG[72], sQy[72];
    __shared__ float swr[A_NUM], sws[A_NUM];
    __shared__ float sgate;

    int tid = threadIdx.x;
    if (tid < 64) {
        int r = tid >> 3, c = tid & 7;
        sQt[r * 9 + c] = g_Qt[tid];
        sG[r * 9 + c]  = g_G[tid];
        sQy[r * 9 + c] = g_Qy[tid];
    } else if (tid < 64 + A_NUM) {
        swr[tid - 64] = g_wr[tid - 64];
        sws[tid - 64] = g_ws[tid - 64];
    } else if (tid == 70) {
        sgate = g_t;
    }
    __syncthreads();

    const size_t b = (size_t)blockIdx.x * 32 + (tid >> 3);
    const int j = tid & 7;

    // ---- load row j of Xt and of each state matrix (coalesced float4) ----
    const float4* xp = reinterpret_cast<const float4*>(x + b * 64 + j * 8);
    float4 xa = xp[0], xb = xp[1];
    float xr[8] = {xa.x, xa.y, xa.z, xa.w, xb.x, xb.y, xb.z, xb.w};

    float m[A_NUM][8];
#pragma unroll
    for (int a = 0; a < A_NUM; a++) {
        const float4* mp = reinterpret_cast<const float4*>(states + b * 320 + a * 64 + j * 8);
        float4 m0 = mp[0], m1 = mp[1];
        m[a][0] = m0.x; m[a][1] = m0.y; m[a][2] = m0.z; m[a][3] = m0.w;
        m[a][4] = m1.x; m[a][5] = m1.y; m[a][6] = m1.z; m[a][7] = m1.w;
    }

    // ---- Yt = sum_a wr[a] * M[a] ----
    float yt[8];
#pragma unroll
    for (int k = 0; k < 8; k++) {
        float s = 0.0f;
#pragma unroll
        for (int a = 0; a < A_NUM; a++) s = fmaf(swr[a], m[a][k], s);
        yt[k] = s;
    }

    // ---- U = Qt * Xt * Qt^T ;  V = G * Yt * G^T (G = Qt*Qr) ----
    float u[8], v[8];
    congruence8(xr, sQt, j, u);
    congruence8(yt, sG, j, v);

    // ---- Phit = (1-t)*U + t*V ----
    const float t = sgate;
    float phit[8];
#pragma unroll
    for (int k = 0; k < 8; k++) phit[k] = fmaf(t, v[k] - u[k], u[k]);

    // ---- Mt[a] = (1-alpha)*M[a] + alpha*Phit ; St = sum ws[a]*Mt[a] ----
    const float alpha[A_NUM] = {0.01f, 0.25f, 0.5f, 0.9f, 0.99f};
    float st[8];
#pragma unroll
    for (int k = 0; k < 8; k++) st[k] = 0.0f;
#pragma unroll
    for (int a = 0; a < A_NUM; a++) {
        float mt[8];
#pragma unroll
        for (int k = 0; k < 8; k++) {
            mt[k] = fmaf(alpha[a], phit[k] - m[a][k], m[a][k]);
            st[k] = fmaf(sws[a], mt[k], st[k]);
        }
        float4* op = reinterpret_cast<float4*>(outst + b * 320 + a * 64 + j * 8);
        op[0] = make_float4(mt[0], mt[1], mt[2], mt[3]);
        op[1] = make_float4(mt[4], mt[5], mt[6], mt[7]);
    }

    // ---- Ot = Qy * St * Qy^T ----
    float ot[8];
    congruence8(st, sQy, j, ot);
    float4* oo = reinterpret_cast<float4*>(out + b * 64 + j * 8);
    oo[0] = make_float4(ot[0], ot[1], ot[2], ot[3]);
    oo[1] = make_float4(ot[4], ot[5], ot[6], ot[7]);
}

extern "C" void kernel_launch(void* const* d_in, const int* in_sizes, int n_in,
                              void* d_out, int out_size) {
    const float* x      = (const float*)d_in[0];
    const float* states = (const float*)d_in[1];
    const float* kr     = (const float*)d_in[2];
    const float* kt     = (const float*)d_in[3];
    const float* kphi   = (const float*)d_in[4];
    const float* ks     = (const float*)d_in[5];
    const float* br     = (const float*)d_in[6];
    const float* bt     = (const float*)d_in[7];
    const float* by     = (const float*)d_in[8];

    const int batch = in_sizes[0] / 64;

    float* out   = (float*)d_out;
    float* outst = out + (size_t)batch * 64;

    spdsru_prologue<<<1, 32>>>(kr, kt, kphi, ks, br, bt, by);

    // 32 batch elements per 256-thread block
    int blocks = batch / 32;
    spdsru_main<<<blocks, 256>>>(x, states, out, outst);
}

// round 4
// speedup vs baseline: 1.8137x; 1.8137x over previous
#include <cuda_runtime.h>

#define A_NUM 5
#define EPSV 1e-10f

// ---------------- batch-independent precomputed parameters ----------------
__device__ float g_Qt[64];
__device__ float g_G[64];   // Qt @ Qr
__device__ float g_Qy[64];
__device__ float g_wr[A_NUM];
__device__ float g_ws[A_NUM];
__device__ float g_t;

// 8x8 Cayley transform: Q = inv(I - Bm) @ (I + Bm), Bm = L - L^T,
// L[i+1][c] = b[i+c] for c in [0, i]  (reference's mapping).
__device__ void cayley8(const float* __restrict__ b, float* __restrict__ Q) {
    float Bm[8][8];
    for (int i = 0; i < 8; i++)
        for (int j = 0; j < 8; j++) Bm[i][j] = 0.0f;
    for (int i = 0; i < 7; i++)
        for (int c = 0; c <= i; c++) Bm[i + 1][c] = b[i + c];

    float A[8][16];
    for (int i = 0; i < 8; i++) {
        for (int j = 0; j < 8; j++) {
            float v = Bm[i][j] - Bm[j][i];
            float d = (i == j) ? 1.0f : 0.0f;
            A[i][j]     = d - v;   // I - Bm
            A[i][j + 8] = d + v;   // I + Bm
        }
    }
    // Gauss-Jordan with partial pivoting
    for (int k = 0; k < 8; k++) {
        int p = k;
        float best = fabsf(A[k][k]);
        for (int r = k + 1; r < 8; r++) {
            float v = fabsf(A[r][k]);
            if (v > best) { best = v; p = r; }
        }
        if (p != k) {
            for (int j = 0; j < 16; j++) {
                float tmp = A[k][j]; A[k][j] = A[p][j]; A[p][j] = tmp;
            }
        }
        float inv = 1.0f / A[k][k];
        for (int j = 0; j < 16; j++) A[k][j] *= inv;
        for (int r = 0; r < 8; r++) {
            if (r == k) continue;
            float f = A[r][k];
            for (int j = 0; j < 16; j++) A[r][j] -= f * A[k][j];
        }
    }
    for (int i = 0; i < 8; i++)
        for (int j = 0; j < 8; j++) Q[i * 8 + j] = A[i][j + 8];
}

__global__ void spdsru_prologue(const float* __restrict__ kr,
                                const float* __restrict__ kt,
                                const float* __restrict__ kphi,
                                const float* __restrict__ ks,
                                const float* __restrict__ br,
                                const float* __restrict__ bt,
                                const float* __restrict__ by) {
    __shared__ float sQr[64];
    __shared__ float sQt[64];
    int tid = threadIdx.x;
    if (tid < 3) {
        const float* bias = (tid == 0) ? br : ((tid == 1) ? bt : by);
        float Q[64];
        cayley8(bias, Q);
        if (tid == 0) {
            for (int i = 0; i < 64; i++) sQr[i] = Q[i];
        } else if (tid == 1) {
            for (int i = 0; i < 64; i++) { sQt[i] = Q[i]; g_Qt[i] = Q[i]; }
        } else {
            for (int i = 0; i < 64; i++) g_Qy[i] = Q[i];
        }
    }
    __syncthreads();
    if (tid == 0) {
        // G = Qt @ Qr
        for (int i = 0; i < 8; i++) {
            for (int j = 0; j < 8; j++) {
                float s = 0.0f;
                for (int k = 0; k < 8; k++) s += sQt[i * 8 + k] * sQr[k * 8 + j];
                g_G[i * 8 + j] = s;
            }
        }
        float r2[A_NUM], s2[A_NUM], sr = 0.0f, ss = 0.0f;
        for (int a = 0; a < A_NUM; a++) {
            r2[a] = kr[a] * kr[a]; sr += r2[a];
            s2[a] = ks[a] * ks[a]; ss += s2[a];
        }
        float ir = 1.0f / (sr + EPSV);
        float is = 1.0f / (ss + EPSV);
        for (int a = 0; a < A_NUM; a++) {
            g_wr[a] = r2[a] * ir;
            g_ws[a] = s2[a] * is;
        }
        float t2 = kt[0] * kt[0];
        g_t = t2 / (t2 + kphi[0] * kphi[0] + EPSV);
    }
}

// ---------------- main streaming kernel ----------------
// 128 threads/block = 4 warps = 16 batch elements. Thread j of an 8-thread
// group owns row j of every 8x8 matrix.
//
// Congruence C = Q * A * Q^T, MIO-lean version:
//   stage 1: B_row_j = A_row_j * Q^T      (local FMA; Q broadcast via LDS.128)
//   stage 2: row j -> smem (STS.128), syncwarp, then
//            C_row_j = sum_i Q[j][i] * B_row_i  (B rows via LDS.128)
//
// NOTE: the B-buffer pointers are deliberately NOT __restrict__ — the write
// slot aliases the read window; __syncwarp() provides the ordering.

struct SQ {
    float4 packed[16];  // Q row-major as float4 pairs (broadcast reads)
    float  padded[72];  // Q row-major stride 9 (per-row scalar reads)
};

__device__ __forceinline__ void congruence8(const float* a,
                                            const SQ* Q,
                                            int j,
                                            float* bufbase,  // smem group tile (72 floats)
                                            float* c) {
    float bb[8];
#pragma unroll
    for (int k = 0; k < 8; k++) {
        float4 q0 = Q->packed[2 * k];
        float4 q1 = Q->packed[2 * k + 1];
        float s = a[0] * q0.x;
        s = fmaf(a[1], q0.y, s);
        s = fmaf(a[2], q0.z, s);
        s = fmaf(a[3], q0.w, s);
        s = fmaf(a[4], q1.x, s);
        s = fmaf(a[5], q1.y, s);
        s = fmaf(a[6], q1.z, s);
        s = fmaf(a[7], q1.w, s);
        bb[k] = s;
    }
    __syncwarp();   // previous congruence's reads of this buffer are done
    float4* bw = reinterpret_cast<float4*>(bufbase + j * 8);
    bw[0] = make_float4(bb[0], bb[1], bb[2], bb[3]);
    bw[1] = make_float4(bb[4], bb[5], bb[6], bb[7]);
    __syncwarp();   // all 8 rows visible before gathering
#pragma unroll
    for (int k = 0; k < 8; k++) c[k] = 0.0f;
#pragma unroll
    for (int i = 0; i < 8; i++) {
        float qji = Q->padded[j * 9 + i];
        const float4* br = reinterpret_cast<const float4*>(bufbase + i * 8);
        float4 b0 = br[0];
        float4 b1 = br[1];
        c[0] = fmaf(qji, b0.x, c[0]);
        c[1] = fmaf(qji, b0.y, c[1]);
        c[2] = fmaf(qji, b0.z, c[2]);
        c[3] = fmaf(qji, b0.w, c[3]);
        c[4] = fmaf(qji, b1.x, c[4]);
        c[5] = fmaf(qji, b1.y, c[5]);
        c[6] = fmaf(qji, b1.z, c[6]);
        c[7] = fmaf(qji, b1.w, c[7]);
    }
}

__global__ void __launch_bounds__(128)
spdsru_main(const float* __restrict__ x,
            const float* __restrict__ states,
            float* __restrict__ out,
            float* __restrict__ outst) {
    __shared__ SQ sQt, sG, sQy;
    __shared__ float sB[16 * 72];   // 4 warps * 4 groups * 72 floats
    __shared__ float swr[A_NUM], sws[A_NUM];
    __shared__ float sgate;

    const int tid = threadIdx.x;
    if (tid < 64) {
        int r = tid >> 3, cc = tid & 7;
        float qt = g_Qt[tid], gg = g_G[tid], qy = g_Qy[tid];
        reinterpret_cast<float*>(sQt.packed)[tid] = qt;
        reinterpret_cast<float*>(sG.packed)[tid]  = gg;
        reinterpret_cast<float*>(sQy.packed)[tid] = qy;
        sQt.padded[r * 9 + cc] = qt;
        sG.padded[r * 9 + cc]  = gg;
        sQy.padded[r * 9 + cc] = qy;
    } else if (tid < 64 + A_NUM) {
        swr[tid - 64] = g_wr[tid - 64];
        sws[tid - 64] = g_ws[tid - 64];
    } else if (tid == 70) {
        sgate = g_t;
    }
    __syncthreads();

    const size_t b = (size_t)blockIdx.x * 16 + (tid >> 3);
    const int j = tid & 7;
    const int grp = tid >> 3;            // 0..15 (warp*4+group)
    float* bufbase = sB + grp * 72;      // this group's 8x8 tile

    // ---- load row j of Xt and of each state matrix (coalesced float4) ----
    const float4* xp = reinterpret_cast<const float4*>(x + b * 64 + j * 8);
    float4 xa = xp[0], xb = xp[1];
    float xr[8] = {xa.x, xa.y, xa.z, xa.w, xb.x, xb.y, xb.z, xb.w};

    float m[A_NUM][8];
#pragma unroll
    for (int a = 0; a < A_NUM; a++) {
        const float4* mp = reinterpret_cast<const float4*>(states + b * 320 + a * 64 + j * 8);
        float4 m0 = mp[0], m1 = mp[1];
        m[a][0] = m0.x; m[a][1] = m0.y; m[a][2] = m0.z; m[a][3] = m0.w;
        m[a][4] = m1.x; m[a][5] = m1.y; m[a][6] = m1.z; m[a][7] = m1.w;
    }

    // ---- Yt = sum_a wr[a] * M[a] ----
    float yt[8];
#pragma unroll
    for (int k = 0; k < 8; k++) {
        float s = 0.0f;
#pragma unroll
        for (int a = 0; a < A_NUM; a++) s = fmaf(swr[a], m[a][k], s);
        yt[k] = s;
    }

    // ---- U = Qt*Xt*Qt^T ;  V = G*Yt*G^T  (G = Qt*Qr) ----
    float u[8], v[8];
    congruence8(xr, &sQt, j, bufbase, u);
    congruence8(yt, &sG, j, bufbase, v);

    // ---- Phit = (1-t)*U + t*V ----
    const float t = sgate;
    float phit[8];
#pragma unroll
    for (int k = 0; k < 8; k++) phit[k] = fmaf(t, v[k] - u[k], u[k]);

    // ---- Mt[a] = (1-alpha)*M[a] + alpha*Phit ; St = sum ws[a]*Mt[a] ----
    const float alpha[A_NUM] = {0.01f, 0.25f, 0.5f, 0.9f, 0.99f};
    float st[8];
#pragma unroll
    for (int k = 0; k < 8; k++) st[k] = 0.0f;
#pragma unroll
    for (int a = 0; a < A_NUM; a++) {
        float mt[8];
#pragma unroll
        for (int k = 0; k < 8; k++) {
            mt[k] = fmaf(alpha[a], phit[k] - m[a][k], m[a][k]);
            st[k] = fmaf(sws[a], mt[k], st[k]);
        }
        float4* op = reinterpret_cast<float4*>(outst + b * 320 + a * 64 + j * 8);
        op[0] = make_float4(mt[0], mt[1], mt[2], mt[3]);
        op[1] = make_float4(mt[4], mt[5], mt[6], mt[7]);
    }

    // ---- Ot = Qy * St * Qy^T ----
    float ot[8];
    congruence8(st, &sQy, j, bufbase, ot);
    float4* oo = reinterpret_cast<float4*>(out + b * 64 + j * 8);
    oo[0] = make_float4(ot[0], ot[1], ot[2], ot[3]);
    oo[1] = make_float4(ot[4], ot[5], ot[6], ot[7]);
}

extern "C" void kernel_launch(void* const* d_in, const int* in_sizes, int n_in,
                              void* d_out, int out_size) {
    const float* x      = (const float*)d_in[0];
    const float* states = (const float*)d_in[1];
    const float* kr     = (const float*)d_in[2];
    const float* kt     = (const float*)d_in[3];
    const float* kphi   = (const float*)d_in[4];
    const float* ks     = (const float*)d_in[5];
    const float* br     = (const float*)d_in[6];
    const float* bt     = (const float*)d_in[7];
    const float* by     = (const float*)d_in[8];

    const int batch = in_sizes[0] / 64;

    float* out   = (float*)d_out;
    float* outst = out + (size_t)batch * 64;

    spdsru_prologue<<<1, 32>>>(kr, kt, kphi, ks, br, bt, by);

    // 16 batch elements per 128-thread block
    int blocks = batch / 16;
    spdsru_main<<<blocks, 128>>>(x, states, out, outst);
}